// round 9
// baseline (speedup 1.0000x reference)
#include <cuda_runtime.h>
#include <cstdint>

// Problem dims (fixed: T=2048, B=32, D=512)
#define T_DIM 2048
#define B_DIM 32
#define D_DIM 512
#define M_DIM (T_DIM * B_DIM)   // 65536 GEMM rows
#define BD    (B_DIM * D_DIM)   // 16384 scan lanes

// Scratch: Y = x @ W^T + b (fp32, 134 MB)
__device__ float g_Y[(size_t)M_DIM * D_DIM];

// ---------------------------------------------------------------------------
// SGEMM: Y[m,e] = sum_k X[m,k]*W[e,k] + bias[e]
// CONSTRAINT: per output, fp32 fmaf chain with k strictly ascending 0..511
// (bit-matches the reference rounding; any reassociation flips spikes).
// CTA 128m x 256n x k16, 256 threads, 8 warps (4m x 2n), thread tile 8m x 16n,
// fma.rn.f32x2 over n-pairs. This round: A duplicated in smem (LDS.64 feeds
// the f32x2 multiplier directly, no pack MOVs), padded smem rows (STS bank
// relief), and unroll-4 inner loop (L0 I-cache resident body).
// ---------------------------------------------------------------------------
#define BMT 128
#define BNT 256
#define BKT 16
#define NKT (D_DIM / BKT)   // 32
#define AROW 258            // 128 m-values duplicated (256) + 2 pad; 1032B rows (8B-aligned)
#define BROW 260            // 256 n-values + 4 pad; 1040B rows (16B-aligned)

typedef unsigned long long u64t;

__device__ __forceinline__ void ffma2(u64t& d, u64t a, u64t b) {
    asm("fma.rn.f32x2 %0, %1, %2, %0;" : "+l"(d) : "l"(a), "l"(b));
}
__device__ __forceinline__ void unpack2(u64t p, float& lo, float& hi) {
    asm("mov.b64 {%0, %1}, %2;" : "=f"(lo), "=f"(hi) : "l"(p));
}

__global__ __launch_bounds__(256, 1)
void sgemm_kernel(const float* __restrict__ X, const float* __restrict__ Wm,
                  const float* __restrict__ bias) {
    __shared__ __align__(16) float As[2][BKT][AROW];   // ~33 KB (duplicated A)
    __shared__ __align__(16) float Bs[2][BKT][BROW];   // ~33 KB

    const int tid = threadIdx.x;
    const int bm  = blockIdx.x * BMT;
    const int bn  = blockIdx.y * BNT;

    // 8 warps = 4(m) x 2(n); warp tile 32m x 128n; thread tile 8m x 16n
    const int wid    = tid >> 5;
    const int lane   = tid & 31;
    const int warp_m = wid >> 1;              // 0..3
    const int warp_n = wid & 1;               // 0..1
    const int lm     = lane >> 3;             // 0..3
    const int ln     = lane & 7;              // 0..7
    const int tm0    = warp_m * 32 + lm * 8;  // 8 consecutive m rows
    const int bn0    = warp_n * 128 + ln * 4; // + q*32, q=0..3 (4 cols each)

    // gmem load mapping: 4 threads per row (one float4 of k each)
    const int gr = tid >> 2;                  // 0..63
    const int gk = (tid & 3) << 2;            // 0,4,8,12

    const float* Xg = X  + (size_t)(bm + gr) * D_DIM + gk;
    const float* Wg = Wm + (size_t)(bn + gr) * D_DIM + gk;

    u64t acc[8][8];
#pragma unroll
    for (int i = 0; i < 8; i++)
#pragma unroll
        for (int j = 0; j < 8; j++) acc[i][j] = 0ull;

    // prologue: chunk 0 -> buffer 0 (A stored duplicated)
    {
        float4 a0 = *(const float4*)(Xg);
        float4 a1 = *(const float4*)(Xg + (size_t)64 * D_DIM);
#pragma unroll
        for (int c = 0; c < 4; c++) {
            float v0 = ((const float*)&a0)[c];
            float v1 = ((const float*)&a1)[c];
            *(float2*)&As[0][gk + c][2 * gr]        = make_float2(v0, v0);
            *(float2*)&As[0][gk + c][2 * (gr + 64)] = make_float2(v1, v1);
        }
#pragma unroll
        for (int s = 0; s < 4; s++) {
            float4 b = *(const float4*)(Wg + (size_t)(s * 64) * D_DIM);
#pragma unroll
            for (int c = 0; c < 4; c++)
                Bs[0][gk + c][gr + s * 64] = ((const float*)&b)[c];
        }
    }
    __syncthreads();

    for (int kt = 1; kt <= NKT; kt++) {
        const int buf = (kt - 1) & 1;

        float4 na0, na1, nb[4];
        if (kt < NKT) {
            const int k0 = kt * BKT;
            na0 = *(const float4*)(Xg + k0);
            na1 = *(const float4*)(Xg + k0 + (size_t)64 * D_DIM);
#pragma unroll
            for (int s = 0; s < 4; s++)
                nb[s] = *(const float4*)(Wg + k0 + (size_t)(s * 64) * D_DIM);
        }

#pragma unroll 4
        for (int k = 0; k < BKT; k++) {
            // A: 8 LDS.64 of pre-duplicated pairs (no pack MOVs)
            u64t ad[8];
#pragma unroll
            for (int i = 0; i < 8; i++)
                ad[i] = *(const u64t*)&As[buf][k][2 * (tm0 + i)];

            u64t bp[8];
#pragma unroll
            for (int q = 0; q < 4; q++) {
                // 8 lanes (ln) cover one contiguous 128B block: conflict-free
                ulonglong2 b2 = *(const ulonglong2*)&Bs[buf][k][bn0 + q * 32];
                bp[q * 2 + 0] = b2.x;
                bp[q * 2 + 1] = b2.y;
            }

#pragma unroll
            for (int i = 0; i < 8; i++)
#pragma unroll
                for (int j = 0; j < 8; j++)
                    ffma2(acc[i][j], ad[i], bp[j]);
        }

        if (kt < NKT) {
            const int nbuf = kt & 1;
#pragma unroll
            for (int c = 0; c < 4; c++) {
                float v0 = ((const float*)&na0)[c];
                float v1 = ((const float*)&na1)[c];
                *(float2*)&As[nbuf][gk + c][2 * gr]        = make_float2(v0, v0);
                *(float2*)&As[nbuf][gk + c][2 * (gr + 64)] = make_float2(v1, v1);
            }
#pragma unroll
            for (int s = 0; s < 4; s++)
#pragma unroll
                for (int c = 0; c < 4; c++)
                    Bs[nbuf][gk + c][gr + s * 64] = ((const float*)&nb[s])[c];
        }
        __syncthreads();
    }

    // epilogue: + bias (scalar fp32 adds, bit-identical), store Y
#pragma unroll
    for (int q = 0; q < 4; q++) {
        const int col = bn + bn0 + q * 32;
        const float4 bi = *(const float4*)(bias + col);
#pragma unroll
        for (int i = 0; i < 8; i++) {
            float v0, v1, v2, v3;
            unpack2(acc[i][q * 2 + 0], v0, v1);
            unpack2(acc[i][q * 2 + 1], v2, v3);
            float4 o = {v0 + bi.x, v1 + bi.y, v2 + bi.z, v3 + bi.w};
            *(float4*)(g_Y + (size_t)(bm + tm0 + i) * D_DIM + col) = o;
        }
    }
}

// ---------------------------------------------------------------------------
// Fused fwd+bwd LIF scan, time-chunked with warm-up (verified exact).
// ---------------------------------------------------------------------------
#define L_CH  256
#define W_UP  96
#define NCH   (T_DIM / L_CH)
#define UNR   16

__device__ __forceinline__ void lif_step(float& v, float c, bool& s) {
    v = v + (c - v) * 0.5f;
    s = (v >= 1.0f);
    v = s ? 0.0f : v;
}

__global__ void scan_kernel(float* __restrict__ out) {
    const int l  = blockIdx.x * blockDim.x + threadIdx.x;
    const int t0 = blockIdx.y * L_CH;
    unsigned fb[L_CH / 32];

    float v = 0.0f;
    {
        const int tb = (t0 - W_UP < 0) ? 0 : (t0 - W_UP);
        for (int tw = tb; tw < t0; tw += UNR) {
            float c[UNR];
#pragma unroll
            for (int i = 0; i < UNR; i++) c[i] = g_Y[(size_t)(tw + i) * BD + l];
#pragma unroll
            for (int i = 0; i < UNR; i++) { bool s; lif_step(v, c[i], s); }
        }
#pragma unroll
        for (int w = 0; w < L_CH / 32; w++) {
            unsigned bits = 0;
#pragma unroll 1
            for (int h = 0; h < 2; h++) {
                float c[UNR];
#pragma unroll
                for (int i = 0; i < UNR; i++)
                    c[i] = g_Y[(size_t)(t0 + w * 32 + h * UNR + i) * BD + l];
#pragma unroll
                for (int i = 0; i < UNR; i++) {
                    bool s; lif_step(v, c[i], s);
                    bits |= (unsigned)s << (h * UNR + i);
                }
            }
            fb[w] = bits;
        }
    }

    v = 0.0f;
    {
        const int te = (t0 + L_CH + W_UP > T_DIM) ? T_DIM : (t0 + L_CH + W_UP);
        for (int tw = te; tw > t0 + L_CH; tw -= UNR) {
            float c[UNR];
#pragma unroll
            for (int i = 0; i < UNR; i++) c[i] = g_Y[(size_t)(tw - 1 - i) * BD + l];
#pragma unroll
            for (int i = 0; i < UNR; i++) { bool s; lif_step(v, c[i], s); }
        }
#pragma unroll
        for (int w = L_CH / 32 - 1; w >= 0; w--) {
            const unsigned bits = fb[w];
#pragma unroll 1
            for (int h = 1; h >= 0; h--) {
                float c[UNR];
#pragma unroll
                for (int i = 0; i < UNR; i++)
                    c[i] = g_Y[(size_t)(t0 + w * 32 + h * UNR + (UNR - 1) - i) * BD + l];
#pragma unroll
                for (int i = 0; i < UNR; i++) {
                    const int ti = h * UNR + (UNR - 1) - i;
                    bool s; lif_step(v, c[i], s);
                    out[(size_t)(t0 + w * 32 + ti) * BD + l] =
                        (s ? 1.0f : 0.0f) + (float)((bits >> ti) & 1u);
                }
            }
        }
    }
}

// ---------------------------------------------------------------------------
extern "C" void kernel_launch(void* const* d_in, const int* in_sizes, int n_in,
                              void* d_out, int out_size) {
    const float* x = (const float*)d_in[0];
    const float* W = (const float*)d_in[1];
    const float* b = (const float*)d_in[2];
    float* out = (float*)d_out;

    dim3 ggrid(M_DIM / BMT, D_DIM / BNT);   // (512, 2) = 1024 CTAs
    sgemm_kernel<<<ggrid, 256>>>(x, W, b);

    dim3 sgrid(BD / 256, NCH);              // (64, 8)
    scan_kernel<<<sgrid, 256>>>(out);
}

// round 10
// speedup vs baseline: 1.0211x; 1.0211x over previous
#include <cuda_runtime.h>
#include <cstdint>

// Problem dims (fixed: T=2048, B=32, D=512)
#define T_DIM 2048
#define B_DIM 32
#define D_DIM 512
#define M_DIM (T_DIM * B_DIM)   // 65536 GEMM rows
#define BD    (B_DIM * D_DIM)   // 16384 scan lanes

// Scratch: Y = x @ W^T + b (fp32, 134 MB)
__device__ float g_Y[(size_t)M_DIM * D_DIM];

// ---------------------------------------------------------------------------
// SGEMM: Y[m,e] = sum_k X[m,k]*W[e,k] + bias[e]
// CONSTRAINT: per output, fp32 fmaf chain with k strictly ascending 0..511
// (bit-matches the reference rounding; any reassociation flips spikes).
// Round-8 structure (CTA 128x256x16, 256 thr, 8 warps 4mx2n, tile 8mx16n,
// fma.rn.f32x2, double buffer, full unroll). ONE change vs round 8:
// A stored DUPLICATED in smem ({v,v} pairs) and read via 4x LDS.128/thread-k
// -> f32x2 A operands arrive pre-packed, zero pack MOVs. Dynamic smem 64KB.
// ---------------------------------------------------------------------------
#define BMT 128
#define BNT 256
#define BKT 16
#define NKT (D_DIM / BKT)   // 32
#define A_STRIDE 256        // duplicated: 128 m-rows x 2
#define B_STRIDE 256
#define A_ELEMS  (2 * BKT * A_STRIDE)   // per-buffer*2 handled below
#define SMEM_FLOATS (2 * BKT * A_STRIDE + 2 * BKT * B_STRIDE)  // 16384 floats = 64KB

typedef unsigned long long u64t;

__device__ __forceinline__ void ffma2(u64t& d, u64t a, u64t b) {
    asm("fma.rn.f32x2 %0, %1, %2, %0;" : "+l"(d) : "l"(a), "l"(b));
}
__device__ __forceinline__ void unpack2(u64t p, float& lo, float& hi) {
    asm("mov.b64 {%0, %1}, %2;" : "=f"(lo), "=f"(hi) : "l"(p));
}

__global__ __launch_bounds__(256, 1)
void sgemm_kernel(const float* __restrict__ X, const float* __restrict__ Wm,
                  const float* __restrict__ bias) {
    extern __shared__ __align__(16) float smem[];
    float* As = smem;                        // [2][BKT][A_STRIDE] duplicated
    float* Bs = smem + 2 * BKT * A_STRIDE;   // [2][BKT][B_STRIDE]

    const int tid = threadIdx.x;
    const int bm  = blockIdx.x * BMT;
    const int bn  = blockIdx.y * BNT;

    // 8 warps = 4(m) x 2(n); warp tile 32m x 128n; thread tile 8m x 16n
    const int wid    = tid >> 5;
    const int lane   = tid & 31;
    const int warp_m = wid >> 1;              // 0..3
    const int warp_n = wid & 1;               // 0..1
    const int lm     = lane >> 3;             // 0..3
    const int ln     = lane & 7;              // 0..7
    const int tm0    = warp_m * 32 + lm * 8;  // 8 consecutive m rows
    const int bn0    = warp_n * 128 + ln * 4; // + q*32, q=0..3 (4 cols each)

    // gmem load mapping: 4 threads per row (one float4 of k each)
    const int gr = tid >> 2;                  // 0..63
    const int gk = (tid & 3) << 2;            // 0,4,8,12

    const float* Xg = X  + (size_t)(bm + gr) * D_DIM + gk;
    const float* Wg = Wm + (size_t)(bn + gr) * D_DIM + gk;

    u64t acc[8][8];
#pragma unroll
    for (int i = 0; i < 8; i++)
#pragma unroll
        for (int j = 0; j < 8; j++) acc[i][j] = 0ull;

    // prologue: chunk 0 -> buffer 0 (A duplicated)
    {
        float4 a0 = *(const float4*)(Xg);
        float4 a1 = *(const float4*)(Xg + (size_t)64 * D_DIM);
#pragma unroll
        for (int c = 0; c < 4; c++) {
            float v0 = ((const float*)&a0)[c];
            float v1 = ((const float*)&a1)[c];
            *(float2*)&As[(gk + c) * A_STRIDE + 2 * gr]        = make_float2(v0, v0);
            *(float2*)&As[(gk + c) * A_STRIDE + 2 * (gr + 64)] = make_float2(v1, v1);
        }
#pragma unroll
        for (int s = 0; s < 4; s++) {
            float4 b = *(const float4*)(Wg + (size_t)(s * 64) * D_DIM);
#pragma unroll
            for (int c = 0; c < 4; c++)
                Bs[(gk + c) * B_STRIDE + gr + s * 64] = ((const float*)&b)[c];
        }
    }
    __syncthreads();

    for (int kt = 1; kt <= NKT; kt++) {
        const int buf = (kt - 1) & 1;
        const float* Ab = As + buf * BKT * A_STRIDE;
        const float* Bb = Bs + buf * BKT * B_STRIDE;

        float4 na0, na1, nb[4];
        if (kt < NKT) {
            const int k0 = kt * BKT;
            na0 = *(const float4*)(Xg + k0);
            na1 = *(const float4*)(Xg + k0 + (size_t)64 * D_DIM);
#pragma unroll
            for (int s = 0; s < 4; s++)
                nb[s] = *(const float4*)(Wg + k0 + (size_t)(s * 64) * D_DIM);
        }

#pragma unroll
        for (int k = 0; k < BKT; k++) {
            // A: 4 LDS.128 of pre-duplicated pairs -> 8 packed f32x2 operands
            u64t ad[8];
#pragma unroll
            for (int i = 0; i < 4; i++) {
                ulonglong2 a2 =
                    *(const ulonglong2*)&Ab[k * A_STRIDE + 2 * (tm0 + 2 * i)];
                ad[2 * i + 0] = a2.x;
                ad[2 * i + 1] = a2.y;
            }

            u64t bp[8];
#pragma unroll
            for (int q = 0; q < 4; q++) {
                // 8 lanes (ln) cover one contiguous 128B block: conflict-free
                ulonglong2 b2 = *(const ulonglong2*)&Bb[k * B_STRIDE + bn0 + q * 32];
                bp[q * 2 + 0] = b2.x;
                bp[q * 2 + 1] = b2.y;
            }

#pragma unroll
            for (int i = 0; i < 8; i++)
#pragma unroll
                for (int j = 0; j < 8; j++)
                    ffma2(acc[i][j], ad[i], bp[j]);
        }

        if (kt < NKT) {
            const int nbuf = kt & 1;
            float* An = As + nbuf * BKT * A_STRIDE;
            float* Bn = Bs + nbuf * BKT * B_STRIDE;
#pragma unroll
            for (int c = 0; c < 4; c++) {
                float v0 = ((const float*)&na0)[c];
                float v1 = ((const float*)&na1)[c];
                *(float2*)&An[(gk + c) * A_STRIDE + 2 * gr]        = make_float2(v0, v0);
                *(float2*)&An[(gk + c) * A_STRIDE + 2 * (gr + 64)] = make_float2(v1, v1);
            }
#pragma unroll
            for (int s = 0; s < 4; s++)
#pragma unroll
                for (int c = 0; c < 4; c++)
                    Bn[(gk + c) * B_STRIDE + gr + s * 64] = ((const float*)&nb[s])[c];
        }
        __syncthreads();
    }

    // epilogue: + bias (scalar fp32 adds, bit-identical), store Y
#pragma unroll
    for (int q = 0; q < 4; q++) {
        const int col = bn + bn0 + q * 32;
        const float4 bi = *(const float4*)(bias + col);
#pragma unroll
        for (int i = 0; i < 8; i++) {
            float v0, v1, v2, v3;
            unpack2(acc[i][q * 2 + 0], v0, v1);
            unpack2(acc[i][q * 2 + 1], v2, v3);
            float4 o = {v0 + bi.x, v1 + bi.y, v2 + bi.z, v3 + bi.w};
            *(float4*)(g_Y + (size_t)(bm + tm0 + i) * D_DIM + col) = o;
        }
    }
}

// ---------------------------------------------------------------------------
// Fused fwd+bwd LIF scan, time-chunked with warm-up (verified exact).
// ---------------------------------------------------------------------------
#define L_CH  256
#define W_UP  96
#define NCH   (T_DIM / L_CH)
#define UNR   16

__device__ __forceinline__ void lif_step(float& v, float c, bool& s) {
    v = v + (c - v) * 0.5f;
    s = (v >= 1.0f);
    v = s ? 0.0f : v;
}

__global__ void scan_kernel(float* __restrict__ out) {
    const int l  = blockIdx.x * blockDim.x + threadIdx.x;
    const int t0 = blockIdx.y * L_CH;
    unsigned fb[L_CH / 32];

    float v = 0.0f;
    {
        const int tb = (t0 - W_UP < 0) ? 0 : (t0 - W_UP);
        for (int tw = tb; tw < t0; tw += UNR) {
            float c[UNR];
#pragma unroll
            for (int i = 0; i < UNR; i++) c[i] = g_Y[(size_t)(tw + i) * BD + l];
#pragma unroll
            for (int i = 0; i < UNR; i++) { bool s; lif_step(v, c[i], s); }
        }
#pragma unroll
        for (int w = 0; w < L_CH / 32; w++) {
            unsigned bits = 0;
#pragma unroll 1
            for (int h = 0; h < 2; h++) {
                float c[UNR];
#pragma unroll
                for (int i = 0; i < UNR; i++)
                    c[i] = g_Y[(size_t)(t0 + w * 32 + h * UNR + i) * BD + l];
#pragma unroll
                for (int i = 0; i < UNR; i++) {
                    bool s; lif_step(v, c[i], s);
                    bits |= (unsigned)s << (h * UNR + i);
                }
            }
            fb[w] = bits;
        }
    }

    v = 0.0f;
    {
        const int te = (t0 + L_CH + W_UP > T_DIM) ? T_DIM : (t0 + L_CH + W_UP);
        for (int tw = te; tw > t0 + L_CH; tw -= UNR) {
            float c[UNR];
#pragma unroll
            for (int i = 0; i < UNR; i++) c[i] = g_Y[(size_t)(tw - 1 - i) * BD + l];
#pragma unroll
            for (int i = 0; i < UNR; i++) { bool s; lif_step(v, c[i], s); }
        }
#pragma unroll
        for (int w = L_CH / 32 - 1; w >= 0; w--) {
            const unsigned bits = fb[w];
#pragma unroll 1
            for (int h = 1; h >= 0; h--) {
                float c[UNR];
#pragma unroll
                for (int i = 0; i < UNR; i++)
                    c[i] = g_Y[(size_t)(t0 + w * 32 + h * UNR + (UNR - 1) - i) * BD + l];
#pragma unroll
                for (int i = 0; i < UNR; i++) {
                    const int ti = h * UNR + (UNR - 1) - i;
                    bool s; lif_step(v, c[i], s);
                    out[(size_t)(t0 + w * 32 + ti) * BD + l] =
                        (s ? 1.0f : 0.0f) + (float)((bits >> ti) & 1u);
                }
            }
        }
    }
}

// ---------------------------------------------------------------------------
extern "C" void kernel_launch(void* const* d_in, const int* in_sizes, int n_in,
                              void* d_out, int out_size) {
    const float* x = (const float*)d_in[0];
    const float* W = (const float*)d_in[1];
    const float* b = (const float*)d_in[2];
    float* out = (float*)d_out;

    cudaFuncSetAttribute(sgemm_kernel,
                         cudaFuncAttributeMaxDynamicSharedMemorySize,
                         SMEM_FLOATS * sizeof(float));

    dim3 ggrid(M_DIM / BMT, D_DIM / BNT);   // (512, 2) = 1024 CTAs
    sgemm_kernel<<<ggrid, 256, SMEM_FLOATS * sizeof(float)>>>(x, W, b);

    dim3 sgrid(BD / 256, NCH);              // (64, 8)
    scan_kernel<<<sgrid, 256>>>(out);
}